// round 15
// baseline (speedup 1.0000x reference)
#include <cuda_runtime.h>
#include <cuda_bf16.h>
#include <cstdint>
#include <cstddef>

#define Lc 512
#define Bc 64
#define Ec 512
#define Hc 512
#define Gc 2048
#define Vc 32000

__device__ float         g_xproj[2ULL * Lc * Bc * Gc];
__device__ unsigned      g_bar[2];
__device__ __nv_bfloat16 g_hbf[2][2][2][Bc * Hc];   // [dir][par][hi/lo][b*512+u]
__device__ __nv_bfloat16 g_emb_hi[(size_t)Vc * Ec];
__device__ __nv_bfloat16 g_emb_lo[(size_t)Vc * Ec];
__device__ __nv_bfloat16 g_wih_hi[2][Gc * Ec];
__device__ __nv_bfloat16 g_wih_lo[2][Gc * Ec];

// ---------------- helpers ---------------------------------------------------------
__device__ __forceinline__ float sigmoidf_(float x) { return 1.0f / (1.0f + __expf(-x)); }
__device__ __forceinline__ void atom_add_release(unsigned* p, unsigned v) {
    unsigned old;
    asm volatile("atom.add.release.gpu.u32 %0, [%1], %2;"
                 : "=r"(old) : "l"(p), "r"(v) : "memory");
}
__device__ __forceinline__ unsigned ld_acquire(unsigned* p) {
    unsigned v;
    asm volatile("ld.acquire.gpu.u32 %0, [%1];" : "=r"(v) : "l"(p) : "memory");
    return v;
}
__device__ __forceinline__ uint32_t smem_u32(const void* p) {
    uint32_t a;
    asm("{ .reg .u64 t; cvta.to.shared.u64 t, %1; cvt.u32.u64 %0, t; }"
        : "=r"(a) : "l"(p));
    return a;
}
__device__ __forceinline__ void cp_async16(uint32_t dst, const void* src) {
    asm volatile("cp.async.cg.shared.global [%0], [%1], 16;" :: "r"(dst), "l"(src) : "memory");
}
#define CP_COMMIT() asm volatile("cp.async.commit_group;" ::: "memory")
#define CP_WAIT(n)  asm volatile("cp.async.wait_group %0;" :: "n"(n) : "memory")

#define LDM4(r, a) \
    asm volatile("ldmatrix.sync.aligned.m8n8.x4.shared.b16 {%0,%1,%2,%3}, [%4];" \
                 : "=r"((r)[0]), "=r"((r)[1]), "=r"((r)[2]), "=r"((r)[3]) : "r"(a))
#define LDM2(r, a) \
    asm volatile("ldmatrix.sync.aligned.m8n8.x2.shared.b16 {%0,%1}, [%2];" \
                 : "=r"((r)[0]), "=r"((r)[1]) : "r"(a))
#define MMA16816(d, a, b0, b1) \
    asm volatile("mma.sync.aligned.m16n8k16.row.col.f32.bf16.bf16.f32 " \
                 "{%0,%1,%2,%3},{%4,%5,%6,%7},{%8,%9},{%0,%1,%2,%3};" \
                 : "+f"((d)[0]), "+f"((d)[1]), "+f"((d)[2]), "+f"((d)[3]) \
                 : "r"((a)[0]), "r"((a)[1]), "r"((a)[2]), "r"((a)[3]), "r"(b0), "r"(b1))

__device__ __forceinline__ unsigned short bf16b(__nv_bfloat16 x) {
    return __bfloat16_as_ushort(x);
}

// ---------------- init: barriers + zero h (parity 0, hi+lo, both dirs) -------------
__global__ void k_init() {
    int idx = blockIdx.x * 256 + threadIdx.x;
    if (idx < 2) g_bar[idx] = 0u;
    if (idx < 65536) {
        int d = idx >> 15, j = idx & 32767;
        ((uint32_t*)(&g_hbf[d][0][0][0]))[j] = 0u;
    }
}

// ---------------- k_cvt: fp32 -> exact bf16 (hi, lo) pairs (emb + W_ih) -----------
__global__ __launch_bounds__(256) void k_cvt(const float* __restrict__ emb,
                                             const float* __restrict__ Wf,
                                             const float* __restrict__ Wb) {
    const int EMB4 = (Vc * Ec) / 4;
    const int W4   = (Gc * Ec) / 4;
    int i = blockIdx.x * 256 + threadIdx.x;
    if (i >= EMB4 + 2 * W4) return;
    const float4* src; __nv_bfloat16 *dh, *dl; int o;
    if (i < EMB4)           { src = (const float4*)emb; o = i;             dh = g_emb_hi;    dl = g_emb_lo; }
    else if (i < EMB4 + W4) { src = (const float4*)Wf;  o = i - EMB4;      dh = g_wih_hi[0]; dl = g_wih_lo[0]; }
    else                    { src = (const float4*)Wb;  o = i - EMB4 - W4; dh = g_wih_hi[1]; dl = g_wih_lo[1]; }
    float4 v = src[o];
    float xs[4] = {v.x, v.y, v.z, v.w};
    __nv_bfloat16 h4[4], l4[4];
#pragma unroll
    for (int j = 0; j < 4; j++) {
        __nv_bfloat16 hb = __float2bfloat16_rn(xs[j]);
        h4[j] = hb;
        l4[j] = __float2bfloat16_rn(xs[j] - __bfloat162float(hb));
    }
    *(uint2*)(dh + (size_t)o * 4) = *(uint2*)h4;
    *(uint2*)(dl + (size_t)o * 4) = *(uint2*)l4;
}

// ------ k_proj_mma: split-bf16 HMMA GEMM (unchanged, verified R12/R14) --------------
#define PSTR 40
#define PM_SMEM (4 * 128 * PSTR * 2)
__global__ __launch_bounds__(256, 2) void k_proj_mma(
    const int* __restrict__ tokens,
    const float* __restrict__ bihf, const float* __restrict__ bhhf,
    const float* __restrict__ bihb, const float* __restrict__ bhhb)
{
    extern __shared__ __align__(16) __nv_bfloat16 sm[];
    __nv_bfloat16* sAh = sm;
    __nv_bfloat16* sAl = sm + 128 * PSTR;
    __nv_bfloat16* sBh = sm + 2 * 128 * PSTR;
    __nv_bfloat16* sBl = sm + 3 * 128 * PSTR;
    __shared__ float bsm[128];

    const int tid = threadIdx.x, lane = tid & 31, wid = tid >> 5;
    const int dir   = blockIdx.x >> 4;
    const int n0d   = (blockIdx.x & 15) << 7;
    const int mBase = blockIdx.y << 7;
    const int wm = wid >> 1, wn = wid & 1;

    if (tid < 128) {
        const float* bi = dir ? bihb : bihf;
        const float* bh = dir ? bhhb : bhhf;
        bsm[tid] = bi[n0d + tid] + bh[n0d + tid];
    }

    const int ch[2] = {tid * 2, tid * 2 + 1};
    int arow[2], acol[2]; bool tv[2];
    const __nv_bfloat16 *peh[2], *pel[2], *pwh[2], *pwl[2];
    const __nv_bfloat16* Whi = g_wih_hi[dir];
    const __nv_bfloat16* Wlo = g_wih_lo[dir];
#pragma unroll
    for (int i = 0; i < 2; i++) {
        arow[i] = ch[i] >> 2;
        acol[i] = (ch[i] & 3) * 8;
        int tk = tokens[mBase + arow[i]];
        tv[i] = (tk >= 0);
        size_t eo = (size_t)(tv[i] ? tk : 0) * Ec + acol[i];
        peh[i] = g_emb_hi + eo;  pel[i] = g_emb_lo + eo;
        size_t wo = (size_t)(n0d + arow[i]) * Ec + acol[i];
        pwh[i] = Whi + wo;       pwl[i] = Wlo + wo;
    }

    const uint32_t uAh = smem_u32(sAh), uAl = smem_u32(sAl);
    const uint32_t uBh = smem_u32(sBh), uBl = smem_u32(sBl);
    const uint32_t aOff = ((wm * 32 + (lane & 15)) * PSTR + 8 * (lane >> 4)) * 2;
    const uint32_t bOff = ((wn * 64 + ((lane >> 4) << 3) + (lane & 7)) * PSTR
                           + ((lane >> 3) & 1) * 8) * 2;

    float acc[2][8][4];
#pragma unroll
    for (int mi = 0; mi < 2; mi++)
#pragma unroll
        for (int f = 0; f < 8; f++)
#pragma unroll
            for (int q = 0; q < 4; q++) acc[mi][f][q] = 0.0f;

    for (int ks = 0; ks < 16; ks++) {
        const int ko = ks * 32;
        uint4 vah[2], val[2], vbh[2], vbl[2];
#pragma unroll
        for (int i = 0; i < 2; i++) {
            if (tv[i]) { vah[i] = *(const uint4*)(peh[i] + ko);
                         val[i] = *(const uint4*)(pel[i] + ko); }
            else       { vah[i] = make_uint4(0,0,0,0); val[i] = make_uint4(0,0,0,0); }
            vbh[i] = *(const uint4*)(pwh[i] + ko);
            vbl[i] = *(const uint4*)(pwl[i] + ko);
        }
        __syncthreads();
#pragma unroll
        for (int i = 0; i < 2; i++) {
            int so = arow[i] * PSTR + acol[i];
            *(uint4*)(sAh + so) = vah[i];
            *(uint4*)(sAl + so) = val[i];
            *(uint4*)(sBh + so) = vbh[i];
            *(uint4*)(sBl + so) = vbl[i];
        }
        __syncthreads();

#pragma unroll
        for (int kk = 0; kk < 2; kk++) {
            const uint32_t kb = kk * 16 * 2;
            uint32_t ah[2][4], al[2][4];
#pragma unroll
            for (int mi = 0; mi < 2; mi++) {
                LDM4(ah[mi], uAh + aOff + kb + mi * (16 * PSTR * 2));
                LDM4(al[mi], uAl + aOff + kb + mi * (16 * PSTR * 2));
            }
#pragma unroll
            for (int nq = 0; nq < 4; nq++) {
                uint32_t bh[4], bl[4];
                LDM4(bh, uBh + bOff + kb + nq * (16 * PSTR * 2));
                LDM4(bl, uBl + bOff + kb + nq * (16 * PSTR * 2));
#pragma unroll
                for (int mi = 0; mi < 2; mi++) {
                    MMA16816(acc[mi][nq * 2],     ah[mi], bh[0], bh[1]);
                    MMA16816(acc[mi][nq * 2 + 1], ah[mi], bh[2], bh[3]);
                    MMA16816(acc[mi][nq * 2],     ah[mi], bl[0], bl[1]);
                    MMA16816(acc[mi][nq * 2 + 1], ah[mi], bl[2], bl[3]);
                    MMA16816(acc[mi][nq * 2],     al[mi], bh[0], bh[1]);
                    MMA16816(acc[mi][nq * 2 + 1], al[mi], bh[2], bh[3]);
                }
            }
        }
    }

    const int gr = lane >> 2, cn = (lane & 3) * 2;
    float* XO = g_xproj + (size_t)dir * (Lc * Bc * (size_t)Gc);
#pragma unroll
    for (int mi = 0; mi < 2; mi++)
#pragma unroll
        for (int f = 0; f < 8; f++) {
            int nl = wn * 64 + f * 8 + cn;
            float b0 = bsm[nl], b1 = bsm[nl + 1];
            int m0 = mBase + wm * 32 + mi * 16 + gr;
            float* p0 = XO + (size_t)m0 * Gc + n0d + nl;
            *(float2*)p0 = make_float2(acc[mi][f][0] + b0, acc[mi][f][1] + b1);
            float* p1 = p0 + 8 * Gc;
            *(float2*)p1 = make_float2(acc[mi][f][2] + b0, acc[mi][f][3] + b1);
        }
}

// --------- k_rnn: persistent recurrence, HMMA, 512 threads (16 warps, m16n8) -------
// smem bf16 (rows padded to HSTR=520): W_hi[32], W_lo[32], h_hi[64], h_lo[64];
// gsm fp32 [32][65]. 3-term split product (WhHh + WhHl + WlHh).
#define HSTR 520
#define WH0 0
#define WL0 (32 * HSTR)
#define HH0 (64 * HSTR)
#define HL0 (128 * HSTR)
#define GS0 (192 * HSTR)
#define RNN2_SMEM (192 * HSTR * 2 + 32 * 65 * 4)   // 208000 bytes
__global__ __launch_bounds__(512, 1) void k_rnn(
    const float* __restrict__ Whhf, const float* __restrict__ Whhb,
    const float* __restrict__ mask, float* __restrict__ out)
{
    if (blockIdx.x >= 128) return;
    extern __shared__ __align__(16) __nv_bfloat16 sm[];
    float* gsm = (float*)(sm + GS0);

    const int tid  = threadIdx.x;
    const int lane = tid & 31;
    const int wid  = tid >> 5;
    const int dir  = blockIdx.x >> 6;
    const int cid  = blockIdx.x & 63;
    const int u0   = cid << 3;

    const float* __restrict__ Whh = dir ? Whhb : Whhf;

    // convert this CTA's 32 gate rows of W_hh to bf16 hi/lo in smem (padded rows)
    for (int idx = tid; idx < 4096; idx += 512) {
        int r = idx >> 7, q = idx & 127;
        int g = r >> 3, uu = r & 7;
        float4 v = ((const float4*)(Whh + (size_t)(g * Hc + u0 + uu) * Hc))[q];
        float xs[4] = {v.x, v.y, v.z, v.w};
        unsigned short hh[4], ll[4];
#pragma unroll
        for (int j = 0; j < 4; j++) {
            __nv_bfloat16 hb = __float2bfloat16_rn(xs[j]);
            hh[j] = bf16b(hb);
            ll[j] = bf16b(__float2bfloat16_rn(xs[j] - __bfloat162float(hb)));
        }
        *(uint2*)(sm + WH0 + r * HSTR + q * 4) = *(uint2*)hh;
        *(uint2*)(sm + WL0 + r * HSTR + q * 4) = *(uint2*)ll;
    }
    __syncthreads();

    // HMMA geometry: 16 warps = 2(m) x 8(n); warp tile m16 x n8
    const int wm = wid >> 3, wn = wid & 7;
    const uint32_t base = smem_u32(sm);
    const uint32_t uWh = base + WH0 * 2, uWl = base + WL0 * 2;
    const uint32_t uHh = base + HH0 * 2, uHl = base + HL0 * 2;
    const uint32_t aOff = ((wm * 16 + (lane & 15)) * HSTR + 8 * (lane >> 4)) * 2;
    // B: n8 x k16 via ldmatrix.x2 — lanes 0..15 supply addresses
    const uint32_t bOff = ((wn * 8 + (lane & 7)) * HSTR + ((lane >> 3) & 1) * 8) * 2;

    // elementwise ownership: 1 item per thread
    const int eb  = tid >> 3;          // batch 0..63
    const int euu = tid & 7;           // unit 0..7
    float creg = 0.0f;
    int par = 0;

    const float* XP = g_xproj + (size_t)dir * Lc * Bc * Gc;

    float xpi, xpf, xpg, xpo, mk;
    {
        int t0 = dir ? (Lc - 1) : 0;
        const float* xr = XP + ((size_t)t0 * Bc + eb) * Gc + (u0 + euu);
        xpi = xr[0]; xpf = xr[512]; xpg = xr[1024]; xpo = xr[1536];
        mk = mask[t0 * Bc + eb];
    }

    for (int s = 0; s < Lc; s++) {
        const int t = dir ? (Lc - 1 - s) : s;

        // h broadcast: bf16 hi+lo, two k-halves (group = hi&lo of 256 k-values)
        {
            const __nv_bfloat16* hbh = &g_hbf[dir][par][0][0];
            const __nv_bfloat16* hbl = &g_hbf[dir][par][1][0];
#pragma unroll
            for (int half = 0; half < 2; half++) {
#pragma unroll
                for (int j = 0; j < 8; j++) {
                    int c = tid + j * 512;          // 0..4095
                    int buf = c >> 11;              // 0=hi, 1=lo
                    int ci = c & 2047;
                    int row = ci >> 5, k5 = ci & 31;
                    int eoff = row * Hc + half * 256 + k5 * 8;
                    uint32_t dst = (buf ? uHl : uHh)
                                 + (row * HSTR + half * 256 + k5 * 8) * 2;
                    cp_async16(dst, (buf ? hbl : hbh) + eoff);
                }
                CP_COMMIT();
            }
        }

        float acc[4] = {0.f, 0.f, 0.f, 0.f};

        CP_WAIT(1);
        __syncthreads();
#pragma unroll 4
        for (int kc = 0; kc < 16; kc++) {
            uint32_t ah[4], al[4], bh[2], bl[2];
            LDM4(ah, uWh + aOff + kc * 32);
            LDM4(al, uWl + aOff + kc * 32);
            LDM2(bh, uHh + bOff + kc * 32);
            LDM2(bl, uHl + bOff + kc * 32);
            MMA16816(acc, ah, bh[0], bh[1]);
            MMA16816(acc, ah, bl[0], bl[1]);
            MMA16816(acc, al, bh[0], bh[1]);
        }
        CP_WAIT(0);
        __syncthreads();
#pragma unroll 4
        for (int kc = 16; kc < 32; kc++) {
            uint32_t ah[4], al[4], bh[2], bl[2];
            LDM4(ah, uWh + aOff + kc * 32);
            LDM4(al, uWl + aOff + kc * 32);
            LDM2(bh, uHh + bOff + kc * 32);
            LDM2(bl, uHl + bOff + kc * 32);
            MMA16816(acc, ah, bh[0], bh[1]);
            MMA16816(acc, ah, bl[0], bl[1]);
            MMA16816(acc, al, bh[0], bh[1]);
        }

        // write gates to gsm[row][batch]  (m16n8 fragment layout)
        {
            const int gr = lane >> 2, cn = (lane & 3) * 2;
            int row0 = wm * 16 + gr;
            int col0 = wn * 8 + cn;
            gsm[row0 * 65 + col0]           = acc[0];
            gsm[row0 * 65 + col0 + 1]       = acc[1];
            gsm[(row0 + 8) * 65 + col0]     = acc[2];
            gsm[(row0 + 8) * 65 + col0 + 1] = acc[3];
        }
        __syncthreads();

        // LSTM cell: one (eb, euu) item per thread
        float gi = gsm[(euu)      * 65 + eb] + xpi;
        float gf = gsm[(8  + euu) * 65 + eb] + xpf;
        float gg = gsm[(16 + euu) * 65 + eb] + xpg;
        float go = gsm[(24 + euu) * 65 + eb] + xpo;

        float c0 = sigmoidf_(gf) * creg + sigmoidf_(gi) * tanhf(gg);
        float h0 = sigmoidf_(go) * tanhf(c0);
        h0 *= mk; c0 *= mk;
        creg = c0;

        // store h as bf16 hi/lo
        {
            __nv_bfloat16 hb = __float2bfloat16_rn(h0);
            __nv_bfloat16 lb = __float2bfloat16_rn(h0 - __bfloat162float(hb));
            int off = eb * Hc + u0 + euu;
            *(unsigned short*)(&g_hbf[dir][par ^ 1][0][off]) = bf16b(hb);
            *(unsigned short*)(&g_hbf[dir][par ^ 1][1][off]) = bf16b(lb);
        }

        __syncthreads();
        if (tid == 0) atom_add_release(&g_bar[dir], 1u);

        // off-critical-path: output store + next-step prefetch under barrier fill
        out[((size_t)t * Bc + eb) * (2 * Hc) + dir * Hc + (u0 + euu)] = h0;
        if (s + 1 < Lc) {
            int tn = dir ? (Lc - 2 - s) : (s + 1);
            const float* xr = XP + ((size_t)tn * Bc + eb) * Gc + (u0 + euu);
            xpi = xr[0]; xpf = xr[512]; xpg = xr[1024]; xpo = xr[1536];
            mk = mask[tn * Bc + eb];
        }

        if (tid == 0) {
            unsigned target = (unsigned)(s + 1) * 64u;
            while (ld_acquire(&g_bar[dir]) < target) { }
        }
        __syncthreads();
        par ^= 1;
    }
}

// ---------------- launch -------------------------------------------------------------
extern "C" void kernel_launch(void* const* d_in, const int* in_sizes, int n_in,
                              void* d_out, int out_size) {
    const int*   tokens = (const int*)  d_in[0];
    const float* mask   = (const float*)d_in[1];
    const float* emb    = (const float*)d_in[2];
    const float* Wihf   = (const float*)d_in[3];
    const float* Whhf   = (const float*)d_in[4];
    const float* bihf   = (const float*)d_in[5];
    const float* bhhf   = (const float*)d_in[6];
    const float* Wihb   = (const float*)d_in[7];
    const float* Whhb   = (const float*)d_in[8];
    const float* bihb   = (const float*)d_in[9];
    const float* bhhb   = (const float*)d_in[10];
    float* out = (float*)d_out;

    static bool attr_set = false;
    if (!attr_set) {
        cudaFuncSetAttribute(k_rnn, cudaFuncAttributeMaxDynamicSharedMemorySize,
                             RNN2_SMEM);
        attr_set = true;
    }

    k_init<<<256, 256>>>();
    const int CVT = ((Vc * Ec) / 4 + 2 * ((Gc * Ec) / 4) + 255) / 256;
    k_cvt<<<CVT, 256>>>(emb, Wihf, Wihb);
    k_proj_mma<<<dim3(32, (Lc * Bc) / 128), 256, PM_SMEM>>>(tokens, bihf, bhhf,
                                                            bihb, bhhb);
    k_rnn<<<148, 512, RNN2_SMEM>>>(Whhf, Whhb, mask, out);
}

// round 16
// speedup vs baseline: 1.1423x; 1.1423x over previous
#include <cuda_runtime.h>
#include <cuda_bf16.h>
#include <cstdint>
#include <cstddef>

#define Lc 512
#define Bc 64
#define Ec 512
#define Hc 512
#define Gc 2048
#define Vc 32000

__device__ float         g_xproj[2ULL * Lc * Bc * Gc];
__device__ unsigned      g_bar[2];
__device__ __nv_bfloat16 g_hbf[2][2][2][Bc * Hc];   // [dir][par][hi/lo][b*512+u]
__device__ __nv_bfloat16 g_emb_hi[(size_t)Vc * Ec];
__device__ __nv_bfloat16 g_emb_lo[(size_t)Vc * Ec];
__device__ __nv_bfloat16 g_wih_hi[2][Gc * Ec];
__device__ __nv_bfloat16 g_wih_lo[2][Gc * Ec];

// ---------------- helpers ---------------------------------------------------------
__device__ __forceinline__ float sigmoidf_(float x) { return 1.0f / (1.0f + __expf(-x)); }
__device__ __forceinline__ void atom_add_release(unsigned* p, unsigned v) {
    unsigned old;
    asm volatile("atom.add.release.gpu.u32 %0, [%1], %2;"
                 : "=r"(old) : "l"(p), "r"(v) : "memory");
}
__device__ __forceinline__ unsigned ld_acquire(unsigned* p) {
    unsigned v;
    asm volatile("ld.acquire.gpu.u32 %0, [%1];" : "=r"(v) : "l"(p) : "memory");
    return v;
}
__device__ __forceinline__ uint32_t smem_u32(const void* p) {
    uint32_t a;
    asm("{ .reg .u64 t; cvta.to.shared.u64 t, %1; cvt.u32.u64 %0, t; }"
        : "=r"(a) : "l"(p));
    return a;
}
__device__ __forceinline__ void cp_async16(uint32_t dst, const void* src) {
    asm volatile("cp.async.cg.shared.global [%0], [%1], 16;" :: "r"(dst), "l"(src) : "memory");
}
#define CP_COMMIT() asm volatile("cp.async.commit_group;" ::: "memory")
#define CP_WAIT(n)  asm volatile("cp.async.wait_group %0;" :: "n"(n) : "memory")

#define LDM4(r, a) \
    asm volatile("ldmatrix.sync.aligned.m8n8.x4.shared.b16 {%0,%1,%2,%3}, [%4];" \
                 : "=r"((r)[0]), "=r"((r)[1]), "=r"((r)[2]), "=r"((r)[3]) : "r"(a))
#define MMA16816(d, a, b0, b1) \
    asm volatile("mma.sync.aligned.m16n8k16.row.col.f32.bf16.bf16.f32 " \
                 "{%0,%1,%2,%3},{%4,%5,%6,%7},{%8,%9},{%0,%1,%2,%3};" \
                 : "+f"((d)[0]), "+f"((d)[1]), "+f"((d)[2]), "+f"((d)[3]) \
                 : "r"((a)[0]), "r"((a)[1]), "r"((a)[2]), "r"((a)[3]), "r"(b0), "r"(b1))

__device__ __forceinline__ unsigned short bf16b(__nv_bfloat16 x) {
    return __bfloat16_as_ushort(x);
}

// ---------------- init: barriers + zero h (parity 0, hi+lo, both dirs) -------------
__global__ void k_init() {
    int idx = blockIdx.x * 256 + threadIdx.x;
    if (idx < 2) g_bar[idx] = 0u;
    if (idx < 65536) {
        int d = idx >> 15, j = idx & 32767;
        ((uint32_t*)(&g_hbf[d][0][0][0]))[j] = 0u;
    }
}

// ---------------- k_cvt: fp32 -> exact bf16 (hi, lo) pairs (emb + W_ih) -----------
__global__ __launch_bounds__(256) void k_cvt(const float* __restrict__ emb,
                                             const float* __restrict__ Wf,
                                             const float* __restrict__ Wb) {
    const int EMB4 = (Vc * Ec) / 4;
    const int W4   = (Gc * Ec) / 4;
    int i = blockIdx.x * 256 + threadIdx.x;
    if (i >= EMB4 + 2 * W4) return;
    const float4* src; __nv_bfloat16 *dh, *dl; int o;
    if (i < EMB4)           { src = (const float4*)emb; o = i;             dh = g_emb_hi;    dl = g_emb_lo; }
    else if (i < EMB4 + W4) { src = (const float4*)Wf;  o = i - EMB4;      dh = g_wih_hi[0]; dl = g_wih_lo[0]; }
    else                    { src = (const float4*)Wb;  o = i - EMB4 - W4; dh = g_wih_hi[1]; dl = g_wih_lo[1]; }
    float4 v = src[o];
    float xs[4] = {v.x, v.y, v.z, v.w};
    __nv_bfloat16 h4[4], l4[4];
#pragma unroll
    for (int j = 0; j < 4; j++) {
        __nv_bfloat16 hb = __float2bfloat16_rn(xs[j]);
        h4[j] = hb;
        l4[j] = __float2bfloat16_rn(xs[j] - __bfloat162float(hb));
    }
    *(uint2*)(dh + (size_t)o * 4) = *(uint2*)h4;
    *(uint2*)(dl + (size_t)o * 4) = *(uint2*)l4;
}

// ------ k_proj_mma: split-bf16 HMMA GEMM (unchanged, verified R12/R14) --------------
#define PSTR 40
#define PM_SMEM (4 * 128 * PSTR * 2)
__global__ __launch_bounds__(256, 2) void k_proj_mma(
    const int* __restrict__ tokens,
    const float* __restrict__ bihf, const float* __restrict__ bhhf,
    const float* __restrict__ bihb, const float* __restrict__ bhhb)
{
    extern __shared__ __align__(16) __nv_bfloat16 sm[];
    __nv_bfloat16* sAh = sm;
    __nv_bfloat16* sAl = sm + 128 * PSTR;
    __nv_bfloat16* sBh = sm + 2 * 128 * PSTR;
    __nv_bfloat16* sBl = sm + 3 * 128 * PSTR;
    __shared__ float bsm[128];

    const int tid = threadIdx.x, lane = tid & 31, wid = tid >> 5;
    const int dir   = blockIdx.x >> 4;
    const int n0d   = (blockIdx.x & 15) << 7;
    const int mBase = blockIdx.y << 7;
    const int wm = wid >> 1, wn = wid & 1;

    if (tid < 128) {
        const float* bi = dir ? bihb : bihf;
        const float* bh = dir ? bhhb : bhhf;
        bsm[tid] = bi[n0d + tid] + bh[n0d + tid];
    }

    const int ch[2] = {tid * 2, tid * 2 + 1};
    int arow[2], acol[2]; bool tv[2];
    const __nv_bfloat16 *peh[2], *pel[2], *pwh[2], *pwl[2];
    const __nv_bfloat16* Whi = g_wih_hi[dir];
    const __nv_bfloat16* Wlo = g_wih_lo[dir];
#pragma unroll
    for (int i = 0; i < 2; i++) {
        arow[i] = ch[i] >> 2;
        acol[i] = (ch[i] & 3) * 8;
        int tk = tokens[mBase + arow[i]];
        tv[i] = (tk >= 0);
        size_t eo = (size_t)(tv[i] ? tk : 0) * Ec + acol[i];
        peh[i] = g_emb_hi + eo;  pel[i] = g_emb_lo + eo;
        size_t wo = (size_t)(n0d + arow[i]) * Ec + acol[i];
        pwh[i] = Whi + wo;       pwl[i] = Wlo + wo;
    }

    const uint32_t uAh = smem_u32(sAh), uAl = smem_u32(sAl);
    const uint32_t uBh = smem_u32(sBh), uBl = smem_u32(sBl);
    const uint32_t aOff = ((wm * 32 + (lane & 15)) * PSTR + 8 * (lane >> 4)) * 2;
    const uint32_t bOff = ((wn * 64 + ((lane >> 4) << 3) + (lane & 7)) * PSTR
                           + ((lane >> 3) & 1) * 8) * 2;

    float acc[2][8][4];
#pragma unroll
    for (int mi = 0; mi < 2; mi++)
#pragma unroll
        for (int f = 0; f < 8; f++)
#pragma unroll
            for (int q = 0; q < 4; q++) acc[mi][f][q] = 0.0f;

    for (int ks = 0; ks < 16; ks++) {
        const int ko = ks * 32;
        uint4 vah[2], val[2], vbh[2], vbl[2];
#pragma unroll
        for (int i = 0; i < 2; i++) {
            if (tv[i]) { vah[i] = *(const uint4*)(peh[i] + ko);
                         val[i] = *(const uint4*)(pel[i] + ko); }
            else       { vah[i] = make_uint4(0,0,0,0); val[i] = make_uint4(0,0,0,0); }
            vbh[i] = *(const uint4*)(pwh[i] + ko);
            vbl[i] = *(const uint4*)(pwl[i] + ko);
        }
        __syncthreads();
#pragma unroll
        for (int i = 0; i < 2; i++) {
            int so = arow[i] * PSTR + acol[i];
            *(uint4*)(sAh + so) = vah[i];
            *(uint4*)(sAl + so) = val[i];
            *(uint4*)(sBh + so) = vbh[i];
            *(uint4*)(sBl + so) = vbl[i];
        }
        __syncthreads();

#pragma unroll
        for (int kk = 0; kk < 2; kk++) {
            const uint32_t kb = kk * 16 * 2;
            uint32_t ah[2][4], al[2][4];
#pragma unroll
            for (int mi = 0; mi < 2; mi++) {
                LDM4(ah[mi], uAh + aOff + kb + mi * (16 * PSTR * 2));
                LDM4(al[mi], uAl + aOff + kb + mi * (16 * PSTR * 2));
            }
#pragma unroll
            for (int nq = 0; nq < 4; nq++) {
                uint32_t bh[4], bl[4];
                LDM4(bh, uBh + bOff + kb + nq * (16 * PSTR * 2));
                LDM4(bl, uBl + bOff + kb + nq * (16 * PSTR * 2));
#pragma unroll
                for (int mi = 0; mi < 2; mi++) {
                    MMA16816(acc[mi][nq * 2],     ah[mi], bh[0], bh[1]);
                    MMA16816(acc[mi][nq * 2 + 1], ah[mi], bh[2], bh[3]);
                    MMA16816(acc[mi][nq * 2],     ah[mi], bl[0], bl[1]);
                    MMA16816(acc[mi][nq * 2 + 1], ah[mi], bl[2], bl[3]);
                    MMA16816(acc[mi][nq * 2],     al[mi], bh[0], bh[1]);
                    MMA16816(acc[mi][nq * 2 + 1], al[mi], bh[2], bh[3]);
                }
            }
        }
    }

    const int gr = lane >> 2, cn = (lane & 3) * 2;
    float* XO = g_xproj + (size_t)dir * (Lc * Bc * (size_t)Gc);
#pragma unroll
    for (int mi = 0; mi < 2; mi++)
#pragma unroll
        for (int f = 0; f < 8; f++) {
            int nl = wn * 64 + f * 8 + cn;
            float b0 = bsm[nl], b1 = bsm[nl + 1];
            int m0 = mBase + wm * 32 + mi * 16 + gr;
            float* p0 = XO + (size_t)m0 * Gc + n0d + nl;
            *(float2*)p0 = make_float2(acc[mi][f][0] + b0, acc[mi][f][1] + b1);
            float* p1 = p0 + 8 * Gc;
            *(float2*)p1 = make_float2(acc[mi][f][2] + b0, acc[mi][f][3] + b1);
        }
}

// --------- k_rnn: persistent recurrence, HMMA (R14 config, 3-term split) -----------
// smem bf16 (rows padded to HSTR=520): W_hi[32], W_lo[32], h_hi[64], h_lo[64];
// gsm fp32 [32][65]. 8 warps (2m x 4n), warp tile m16 x n16, 256 threads.
// 3-term product WhHh + WhHl + WlHh (AlBl dropped: ~2^-18 rel/step; R12 evidence).
#define HSTR 520
#define WH0 0
#define WL0 (32 * HSTR)
#define HH0 (64 * HSTR)
#define HL0 (128 * HSTR)
#define GS0 (192 * HSTR)
#define RNN2_SMEM (192 * HSTR * 2 + 32 * 65 * 4)   // 208000 bytes
__global__ __launch_bounds__(256, 1) void k_rnn(
    const float* __restrict__ Whhf, const float* __restrict__ Whhb,
    const float* __restrict__ mask, float* __restrict__ out)
{
    if (blockIdx.x >= 128) return;
    extern __shared__ __align__(16) __nv_bfloat16 sm[];
    float* gsm = (float*)(sm + GS0);

    const int tid  = threadIdx.x;
    const int lane = tid & 31;
    const int wid  = tid >> 5;
    const int dir  = blockIdx.x >> 6;
    const int cid  = blockIdx.x & 63;
    const int u0   = cid << 3;

    const float* __restrict__ Whh = dir ? Whhb : Whhf;

    // convert this CTA's 32 gate rows of W_hh to bf16 hi/lo in smem (padded rows)
    for (int idx = tid; idx < 4096; idx += 256) {
        int r = idx >> 7, q = idx & 127;
        int g = r >> 3, uu = r & 7;
        float4 v = ((const float4*)(Whh + (size_t)(g * Hc + u0 + uu) * Hc))[q];
        float xs[4] = {v.x, v.y, v.z, v.w};
        unsigned short hh[4], ll[4];
#pragma unroll
        for (int j = 0; j < 4; j++) {
            __nv_bfloat16 hb = __float2bfloat16_rn(xs[j]);
            hh[j] = bf16b(hb);
            ll[j] = bf16b(__float2bfloat16_rn(xs[j] - __bfloat162float(hb)));
        }
        *(uint2*)(sm + WH0 + r * HSTR + q * 4) = *(uint2*)hh;
        *(uint2*)(sm + WL0 + r * HSTR + q * 4) = *(uint2*)ll;
    }
    __syncthreads();

    // HMMA geometry: 8 warps = 2(m) x 4(n); warp tile m16 x n16
    const int wm = wid >> 2, wn = wid & 3;
    const uint32_t base = smem_u32(sm);
    const uint32_t uWh = base + WH0 * 2, uWl = base + WL0 * 2;
    const uint32_t uHh = base + HH0 * 2, uHl = base + HL0 * 2;
    const uint32_t aOff = ((wm * 16 + (lane & 15)) * HSTR + 8 * (lane >> 4)) * 2;
    const uint32_t bOff = ((wn * 16 + ((lane >> 4) << 3) + (lane & 7)) * HSTR
                           + ((lane >> 3) & 1) * 8) * 2;

    // elementwise ownership
    const int eb  = tid >> 2;
    const int euu = (tid & 3) << 1;
    float creg0 = 0.0f, creg1 = 0.0f;
    int par = 0;

    const float* XP = g_xproj + (size_t)dir * Lc * Bc * Gc;

    float xp00, xp01, xp10, xp11, xp20, xp21, xp30, xp31, mk;
    {
        int t0 = dir ? (Lc - 1) : 0;
        const float* xr = XP + ((size_t)t0 * Bc + eb) * Gc + (u0 + euu);
        xp00 = xr[0];    xp01 = xr[1];
        xp10 = xr[512];  xp11 = xr[513];
        xp20 = xr[1024]; xp21 = xr[1025];
        xp30 = xr[1536]; xp31 = xr[1537];
        mk = mask[t0 * Bc + eb];
    }

    for (int s = 0; s < Lc; s++) {
        const int t = dir ? (Lc - 1 - s) : s;

        // h broadcast: bf16 hi+lo, two k-halves (group = hi&lo of 256 k-values)
        {
            const __nv_bfloat16* hbh = &g_hbf[dir][par][0][0];
            const __nv_bfloat16* hbl = &g_hbf[dir][par][1][0];
#pragma unroll
            for (int half = 0; half < 2; half++) {
#pragma unroll
                for (int j = 0; j < 16; j++) {
                    int c = tid + j * 256;          // 0..4095
                    int buf = c >> 11;              // 0=hi, 1=lo
                    int ci = c & 2047;
                    int row = ci >> 5, k5 = ci & 31;
                    int eoff = row * Hc + half * 256 + k5 * 8;
                    uint32_t dst = (buf ? uHl : uHh)
                                 + (row * HSTR + half * 256 + k5 * 8) * 2;
                    cp_async16(dst, (buf ? hbl : hbh) + eoff);
                }
                CP_COMMIT();
            }
        }

        float acc0[4] = {0.f, 0.f, 0.f, 0.f};
        float acc1[4] = {0.f, 0.f, 0.f, 0.f};

        CP_WAIT(1);
        __syncthreads();
#pragma unroll 4
        for (int kc = 0; kc < 16; kc++) {
            uint32_t ah[4], al[4], bh[4], bl[4];
            LDM4(ah, uWh + aOff + kc * 32);
            LDM4(al, uWl + aOff + kc * 32);
            LDM4(bh, uHh + bOff + kc * 32);
            LDM4(bl, uHl + bOff + kc * 32);
            MMA16816(acc0, ah, bh[0], bh[1]);  MMA16816(acc1, ah, bh[2], bh[3]);
            MMA16816(acc0, ah, bl[0], bl[1]);  MMA16816(acc1, ah, bl[2], bl[3]);
            MMA16816(acc0, al, bh[0], bh[1]);  MMA16816(acc1, al, bh[2], bh[3]);
        }
        CP_WAIT(0);
        __syncthreads();
#pragma unroll 4
        for (int kc = 16; kc < 32; kc++) {
            uint32_t ah[4], al[4], bh[4], bl[4];
            LDM4(ah, uWh + aOff + kc * 32);
            LDM4(al, uWl + aOff + kc * 32);
            LDM4(bh, uHh + bOff + kc * 32);
            LDM4(bl, uHl + bOff + kc * 32);
            MMA16816(acc0, ah, bh[0], bh[1]);  MMA16816(acc1, ah, bh[2], bh[3]);
            MMA16816(acc0, ah, bl[0], bl[1]);  MMA16816(acc1, ah, bl[2], bl[3]);
            MMA16816(acc0, al, bh[0], bh[1]);  MMA16816(acc1, al, bh[2], bh[3]);
        }

        // write gates to gsm[row][batch]
        {
            const int gr = lane >> 2, cn = (lane & 3) * 2;
            int row0 = wm * 16 + gr;
            int col0 = wn * 16 + cn;
            gsm[row0 * 65 + col0]           = acc0[0];
            gsm[row0 * 65 + col0 + 1]       = acc0[1];
            gsm[(row0 + 8) * 65 + col0]     = acc0[2];
            gsm[(row0 + 8) * 65 + col0 + 1] = acc0[3];
            gsm[row0 * 65 + col0 + 8]       = acc1[0];
            gsm[row0 * 65 + col0 + 9]       = acc1[1];
            gsm[(row0 + 8) * 65 + col0 + 8] = acc1[2];
            gsm[(row0 + 8) * 65 + col0 + 9] = acc1[3];
        }
        __syncthreads();

        // LSTM cell for this thread's two (eb, uu) items
        float gi0 = gsm[(euu)          * 65 + eb] + xp00;
        float gf0 = gsm[(8  + euu)     * 65 + eb] + xp10;
        float gg0 = gsm[(16 + euu)     * 65 + eb] + xp20;
        float go0 = gsm[(24 + euu)     * 65 + eb] + xp30;
        float gi1 = gsm[(euu + 1)      * 65 + eb] + xp01;
        float gf1 = gsm[(8  + euu + 1) * 65 + eb] + xp11;
        float gg1 = gsm[(16 + euu + 1) * 65 + eb] + xp21;
        float go1 = gsm[(24 + euu + 1) * 65 + eb] + xp31;

        float c0 = sigmoidf_(gf0) * creg0 + sigmoidf_(gi0) * tanhf(gg0);
        float h0 = sigmoidf_(go0) * tanhf(c0);
        float c1 = sigmoidf_(gf1) * creg1 + sigmoidf_(gi1) * tanhf(gg1);
        float h1 = sigmoidf_(go1) * tanhf(c1);
        h0 *= mk; c0 *= mk; h1 *= mk; c1 *= mk;
        creg0 = c0; creg1 = c1;

        // store h as packed bf16 hi/lo pairs
        {
            __nv_bfloat16 hb0 = __float2bfloat16_rn(h0);
            __nv_bfloat16 hb1 = __float2bfloat16_rn(h1);
            __nv_bfloat16 lb0 = __float2bfloat16_rn(h0 - __bfloat162float(hb0));
            __nv_bfloat16 lb1 = __float2bfloat16_rn(h1 - __bfloat162float(hb1));
            uint32_t hiw = (uint32_t)bf16b(hb0) | ((uint32_t)bf16b(hb1) << 16);
            uint32_t low = (uint32_t)bf16b(lb0) | ((uint32_t)bf16b(lb1) << 16);
            int off = eb * Hc + u0 + euu;
            *(uint32_t*)(&g_hbf[dir][par ^ 1][0][off]) = hiw;
            *(uint32_t*)(&g_hbf[dir][par ^ 1][1][off]) = low;
        }

        __syncthreads();
        if (tid == 0) atom_add_release(&g_bar[dir], 1u);

        // off-critical-path: output store + next-step prefetch under barrier fill
        float* ow = out + ((size_t)t * Bc + eb) * (2 * Hc) + dir * Hc + (u0 + euu);
        ow[0] = h0; ow[1] = h1;
        if (s + 1 < Lc) {
            int tn = dir ? (Lc - 2 - s) : (s + 1);
            const float* xr = XP + ((size_t)tn * Bc + eb) * Gc + (u0 + euu);
            xp00 = xr[0];    xp01 = xr[1];
            xp10 = xr[512];  xp11 = xr[513];
            xp20 = xr[1024]; xp21 = xr[1025];
            xp30 = xr[1536]; xp31 = xr[1537];
            mk = mask[tn * Bc + eb];
        }

        if (tid == 0) {
            unsigned target = (unsigned)(s + 1) * 64u;
            while (ld_acquire(&g_bar[dir]) < target) { }
        }
        __syncthreads();
        par ^= 1;
    }
}

// ---------------- launch -------------------------------------------------------------
extern "C" void kernel_launch(void* const* d_in, const int* in_sizes, int n_in,
                              void* d_out, int out_size) {
    const int*   tokens = (const int*)  d_in[0];
    const float* mask   = (const float*)d_in[1];
    const float* emb    = (const float*)d_in[2];
    const float* Wihf   = (const float*)d_in[3];
    const float* Whhf   = (const float*)d_in[4];
    const float* bihf   = (const float*)d_in[5];
    const float* bhhf   = (const float*)d_in[6];
    const float* Wihb   = (const float*)d_in[7];
    const float* Whhb   = (const float*)d_in[8];
    const float* bihb   = (const float*)d_in[9];
    const float* bhhb   = (const float*)d_in[10];
    float* out = (float*)d_out;

    static bool attr_set = false;
    if (!attr_set) {
        cudaFuncSetAttribute(k_rnn, cudaFuncAttributeMaxDynamicSharedMemorySize,
                             RNN2_SMEM);
        attr_set = true;
    }

    k_init<<<256, 256>>>();
    const int CVT = ((Vc * Ec) / 4 + 2 * ((Gc * Ec) / 4) + 255) / 256;
    k_cvt<<<CVT, 256>>>(emb, Wihf, Wihb);
    k_proj_mma<<<dim3(32, (Lc * Bc) / 128), 256, PM_SMEM>>>(tokens, bihf, bhhf,
                                                            bihb, bhhb);
    k_rnn<<<148, 256, RNN2_SMEM>>>(Whhf, Whhb, mask, out);
}